// round 15
// baseline (speedup 1.0000x reference)
#include <cuda_runtime.h>
#include <cuda_fp16.h>
#include <cstdint>
#include <math.h>

// B=8, S=4096, D=1024, H=8, SEG=4, head_dim=128.
// Padding dead; segment shuffle is a permutation -> segments = consecutive
// 4-token groups. Weights fused: WF = in_proj @ (Wqk|Wqk|Wv), CF = in_proj@b + b.
// All GEMMs single-pass fp16 mma.sync, fp32 accum (measured rel_err 5.49e-4).
// GEMM shape locked by R14: CTA 128x128, 128 thr (4 warps, warp 64x64 ->
// 128 B smem-read/MMA, crossbar-even with the HMMA pipe), 4 stages, 2 CTAs/SM.
// R15: graph fork/join -- x-conversion runs on a second captured stream
// concurrently with weight-prep + fusion GEMM (independent chains).

#define DMODEL 1024
#define NTOK   32768
#define NQKV   3072

#define HSTAGE 4
#define ROWB   80u
#define A_ROWS 128u
#define B_ROWS 128u
#define H_A_OFF 0u
#define H_B_OFF (A_ROWS * ROWB)                     // 10240
#define H_STAGE_BYTES ((A_ROWS + B_ROWS) * ROWB)    // 20480
#define H_SMEM_TOTAL (HSTAGE * H_STAGE_BYTES)       // 81920 -> 2 CTAs/SM

// ------------------------- device scratch (no allocs) -----------------------
__device__ __align__(256) float   g_CF[NQKV];
__device__ __align__(256) __half  g_QKV16[(size_t)NTOK * NQKV];
__device__ __align__(256) __half  g_x16[(size_t)NTOK * DMODEL];
__device__ __align__(256) __half  g_WF16[(size_t)NQKV * DMODEL];
__device__ __align__(256) __half  g_O16[(size_t)NTOK * DMODEL];
__device__ __align__(256) __half  g_ow16[(size_t)DMODEL * DMODEL];
__device__ __align__(256) __half  g_iw16[(size_t)NQKV * DMODEL];
__device__ __align__(256) __half  g_qkT16[(size_t)DMODEL * DMODEL];
__device__ __align__(256) __half  g_vT16[(size_t)DMODEL * DMODEL];

// ------------------------------ helpers -------------------------------------
__device__ __forceinline__ uint32_t smem_u32(const void* p) {
    uint32_t a;
    asm("{ .reg .u64 t; cvta.to.shared.u64 t, %1; cvt.u32.u64 %0, t; }" : "=r"(a) : "l"(p));
    return a;
}
__device__ __forceinline__ void cp16(uint32_t dst, const void* src) {
    asm volatile("cp.async.cg.shared.global [%0], [%1], 16;" :: "r"(dst), "l"(src) : "memory");
}
#define CP_COMMIT() asm volatile("cp.async.commit_group;" ::: "memory")
#define CP_WAIT2()  asm volatile("cp.async.wait_group 2;" ::: "memory")

#define LDSM_X4(R, a) \
    asm volatile("ldmatrix.sync.aligned.m8n8.x4.shared.b16 {%0,%1,%2,%3}, [%4];" \
        : "=r"((R)[0]), "=r"((R)[1]), "=r"((R)[2]), "=r"((R)[3]) : "r"(a))

#define MMA_FP16(d, a, b0, b1) \
    asm volatile("mma.sync.aligned.m16n8k16.row.col.f32.f16.f16.f32 " \
        "{%0,%1,%2,%3}, {%4,%5,%6,%7}, {%8,%9}, {%0,%1,%2,%3};" \
        : "+f"((d)[0]), "+f"((d)[1]), "+f"((d)[2]), "+f"((d)[3]) \
        : "r"((a)[0]), "r"((a)[1]), "r"((a)[2]), "r"((a)[3]), "r"(b0), "r"(b1))

// ----------------------------------------------------------------------------
// Single-pass fp16 GEMM: C[M,Ntot] = A@B^T (+bias).  [R14 optimum shape]
// A: [M,K] fp16 K-major; B: [Ntot,K] fp16 K-major.
// B2 != null: row blocks with m0 >= b2row use B2 instead of B (fusion merge).
// CTA 128x128, BK=32, 128 threads (4 warps, 2Mx2N, warp 64x64), 4 stages,
// 2 CTAs/SM. OUT16=true -> fp16 C16; false -> fp32 C.
// ----------------------------------------------------------------------------
template <bool OUT16>
__global__ void __launch_bounds__(128, 2)
gemm_fp16(const __half* __restrict__ A,
          const __half* __restrict__ B, const __half* __restrict__ B2, int b2row,
          const float* __restrict__ bias, float* __restrict__ C,
          __half* __restrict__ C16, int Ntot, int K)
{
    extern __shared__ char smem[];
    const uint32_t sb = smem_u32(smem);
    const int tid = threadIdx.x, wid = tid >> 5, lane = tid & 31;
    const int m0 = blockIdx.y * 128, n0 = blockIdx.x * 128;
    const int KT = K >> 5;
    const __half* Bp = (B2 != nullptr && m0 >= b2row) ? B2 : B;

    const int wm = (wid & 1) * 64;       // 2 warps in M
    const int wn = (wid >> 1) * 64;      // 2 warps in N
    const int g = lane >> 3, r = lane & 7;

    const uint32_t aRow = (uint32_t)(wm + (g & 1) * 8 + r);
    const uint32_t aCk  = (uint32_t)(g >> 1);
    const uint32_t bRow = (uint32_t)(wn + (g >> 1) * 8 + r);
    const uint32_t bCk  = (uint32_t)(g & 1);

    float acc[4][8][4];
#pragma unroll
    for (int i = 0; i < 4; i++)
#pragma unroll
        for (int j = 0; j < 8; j++)
#pragma unroll
            for (int q = 0; q < 4; q++) acc[i][j][q] = 0.0f;

    auto load_tile = [&](int kt, int s) {
        const int k0 = kt << 5;
        const uint32_t sbase = sb + (uint32_t)s * H_STAGE_BYTES;
#pragma unroll
        for (int q = 0; q < 8; q++) {
            int c = tid + q * 128;
            const __half* src;
            uint32_t dst;
            if (c < 512) {
                int rr = c >> 2, ck = c & 3;
                src = A + (size_t)(m0 + rr) * K + k0 + ck * 8;
                dst = sbase + H_A_OFF + (uint32_t)rr * ROWB + (uint32_t)ck * 16u;
            } else {
                int cc = c - 512;
                int rr = cc >> 2, ck = cc & 3;
                src = Bp + (size_t)(n0 + rr) * K + k0 + ck * 8;
                dst = sbase + H_B_OFF + (uint32_t)rr * ROWB + (uint32_t)ck * 16u;
            }
            cp16(dst, src);
        }
    };

    load_tile(0, 0); CP_COMMIT();
    load_tile(1, 1); CP_COMMIT();
    load_tile(2, 2); CP_COMMIT();

    for (int kt = 0; kt < KT; kt++) {
        CP_WAIT2();
        __syncthreads();
        if (kt + 3 < KT) load_tile(kt + 3, (kt + 3) % HSTAGE);
        CP_COMMIT();

        const uint32_t sbase = sb + (uint32_t)(kt % HSTAGE) * H_STAGE_BYTES;
#pragma unroll
        for (int kc = 0; kc < 2; kc++) {
            uint32_t af[4][4], bf[4][4];
            const uint32_t kofs = (uint32_t)(kc * 2) * 16u;
#pragma unroll
            for (int mi = 0; mi < 4; mi++)
                LDSM_X4(af[mi], sbase + H_A_OFF + (aRow + mi * 16) * ROWB + kofs + aCk * 16u);
#pragma unroll
            for (int bj = 0; bj < 4; bj++)
                LDSM_X4(bf[bj], sbase + H_B_OFF + (bRow + bj * 16) * ROWB + kofs + bCk * 16u);
#pragma unroll
            for (int mi = 0; mi < 4; mi++)
#pragma unroll
                for (int nj = 0; nj < 8; nj++)
                    MMA_FP16(acc[mi][nj], af[mi],
                             bf[nj >> 1][(nj & 1) * 2], bf[nj >> 1][(nj & 1) * 2 + 1]);
        }
    }

    const int rb = lane >> 2, cb = (lane & 3) * 2;
#pragma unroll
    for (int mi = 0; mi < 4; mi++) {
#pragma unroll
        for (int nj = 0; nj < 8; nj++) {
            int row0 = m0 + wm + mi * 16 + rb;
            int col = n0 + wn + nj * 8 + cb;
            float b0 = bias ? bias[col] : 0.0f;
            float b1 = bias ? bias[col + 1] : 0.0f;
            float v0 = acc[mi][nj][0] + b0, v1 = acc[mi][nj][1] + b1;
            float v2 = acc[mi][nj][2] + b0, v3 = acc[mi][nj][3] + b1;
            if (OUT16) {
                *(__half2*)(C16 + (size_t)row0 * Ntot + col) =
                    __halves2half2(__float2half_rn(v0), __float2half_rn(v1));
                *(__half2*)(C16 + (size_t)(row0 + 8) * Ntot + col) =
                    __halves2half2(__float2half_rn(v2), __float2half_rn(v3));
            } else {
                *(float2*)(C + (size_t)row0 * Ntot + col) = make_float2(v0, v1);
                *(float2*)(C + (size_t)(row0 + 8) * Ntot + col) = make_float2(v2, v3);
            }
        }
    }
}

// ------------------- prep, split into two independent branches ---------------
#define N4_X  (NTOK * DMODEL / 4)            // 8388608
#define N4_IW (NQKV * DMODEL / 4)            // 786432
#define N4_OW (DMODEL * DMODEL / 4)          // 262144
#define XCONV_BLOCKS (N4_X / 1024)           // 8192 (256 thr x 4 f4)
#define WCONV_BLOCKS ((N4_IW + N4_OW) / 1024)// 1024
#define TRANS_BLOCKS 2048                    // 32*32*2
#define BIAS_BLOCKS 384
#define WPREP_BLOCKS (WCONV_BLOCKS + TRANS_BLOCKS + BIAS_BLOCKS)

// x fp32 -> fp16, 4x float4 per thread
__global__ void xconv_kernel(const float* __restrict__ x)
{
    int j0 = blockIdx.x * 1024 + threadIdx.x;
#pragma unroll
    for (int q = 0; q < 4; q++) {
        int j = j0 + q * 256;
        float4 v = ((const float4*)x)[j];
        ((__half2*)g_x16)[2 * j + 0] = __halves2half2(__float2half_rn(v.x), __float2half_rn(v.y));
        ((__half2*)g_x16)[2 * j + 1] = __halves2half2(__float2half_rn(v.z), __float2half_rn(v.w));
    }
}

// weights branch: iw/ow converts + transposes + fused bias
__global__ void wprep_kernel(const float* __restrict__ iw,
                             const float* __restrict__ ow,
                             const float* __restrict__ qk_w,
                             const float* __restrict__ v_w,
                             const float* __restrict__ in_b,
                             const float* __restrict__ bqk,
                             const float* __restrict__ bv)
{
    __shared__ float t[32][33];
    const int b = blockIdx.x, tid = threadIdx.x;

    if (b < WCONV_BLOCKS) {
        int j0 = b * 1024 + tid;
#pragma unroll
        for (int q = 0; q < 4; q++) {
            int j = j0 + q * 256;
            const float* in;
            __half* out;
            if (j < N4_IW) { in = iw; out = g_iw16; }
            else { j -= N4_IW; in = ow; out = g_ow16; }
            float4 v = ((const float4*)in)[j];
            ((__half2*)out)[2 * j + 0] = __halves2half2(__float2half_rn(v.x), __float2half_rn(v.y));
            ((__half2*)out)[2 * j + 1] = __halves2half2(__float2half_rn(v.z), __float2half_rn(v.w));
        }
    } else if (b < WCONV_BLOCKS + TRANS_BLOCKS) {
        int bb = b - WCONV_BLOCKS;
        int z = bb >> 10, rem = bb & 1023;
        const float* W = z ? v_w : qk_w;
        __half* T = z ? g_vT16 : g_qkT16;
        int bx = (rem & 31) * 32, by = (rem >> 5) * 32;
        int tx = tid & 31, ty = tid >> 5;     // 32 x 8
        for (int j = ty; j < 32; j += 8)
            t[j][tx] = W[(size_t)(by + j) * DMODEL + bx + tx];
        __syncthreads();
        for (int j = ty; j < 32; j += 8)
            T[(size_t)(bx + j) * DMODEL + by + tx] = __float2half_rn(t[tx][j]);
    } else {
        int bb = b - WCONV_BLOCKS - TRANS_BLOCKS;
        int gw = (bb * 256 + tid) >> 5;
        int lane = tid & 31;
        if (gw < NQKV) {
            const float* bvec = (gw < 2048) ? bqk : bv;
            const float* Arow = iw + (size_t)gw * DMODEL;
            float s = 0.0f;
            for (int j = lane; j < DMODEL; j += 32) s += Arow[j] * bvec[j];
#pragma unroll
            for (int off = 16; off; off >>= 1) s += __shfl_xor_sync(0xffffffffu, s, off);
            if (lane == 0) g_CF[gw] = s + in_b[gw];
        }
    }
}

// -------- segment attention (SEG=4, per head), 8B vector loads/stores --------
__global__ void attn_kernel()
{
    int gw   = (int)((blockIdx.x * blockDim.x + threadIdx.x) >> 5);
    int lane = threadIdx.x & 31;
    if (gw >= (NTOK / 4) * 8) return;
    int seg = gw >> 3, h = gw & 7, t0 = seg << 2;

    const __half* base = g_QKV16 + (size_t)t0 * NQKV + h * 128 + lane * 4;
    float4 q[4], k[4], v[4];
#pragma unroll
    for (int i = 0; i < 4; i++) {
        uint2 qr = *(const uint2*)(base + (size_t)i * NQKV);
        uint2 kr = *(const uint2*)(base + (size_t)i * NQKV + 1024);
        uint2 vr = *(const uint2*)(base + (size_t)i * NQKV + 2048);
        float2 q0 = __half22float2(*(const __half2*)&qr.x), q1 = __half22float2(*(const __half2*)&qr.y);
        float2 k0 = __half22float2(*(const __half2*)&kr.x), k1 = __half22float2(*(const __half2*)&kr.y);
        float2 v0 = __half22float2(*(const __half2*)&vr.x), v1 = __half22float2(*(const __half2*)&vr.y);
        q[i] = make_float4(q0.x, q0.y, q1.x, q1.y);
        k[i] = make_float4(k0.x, k0.y, k1.x, k1.y);
        v[i] = make_float4(v0.x, v0.y, v1.x, v1.y);
    }
    float s[4][4];
#pragma unroll
    for (int i = 0; i < 4; i++)
#pragma unroll
        for (int j = 0; j < 4; j++)
            s[i][j] = q[i].x * k[j].x + q[i].y * k[j].y + q[i].z * k[j].z + q[i].w * k[j].w;
#pragma unroll
    for (int off = 16; off; off >>= 1)
#pragma unroll
        for (int i = 0; i < 4; i++)
#pragma unroll
            for (int j = 0; j < 4; j++)
                s[i][j] += __shfl_xor_sync(0xffffffffu, s[i][j], off);

    const float scale = 0.08838834764831845f;
    float p[4][4];
#pragma unroll
    for (int i = 0; i < 4; i++) {
        float m = -1e30f;
#pragma unroll
        for (int j = 0; j < 4; j++) {
            float sv = (j == i) ? -1e30f : s[i][j] * scale;
            p[i][j] = sv; m = fmaxf(m, sv);
        }
        float sum = 0.0f;
#pragma unroll
        for (int j = 0; j < 4; j++) { p[i][j] = expf(p[i][j] - m); sum += p[i][j]; }
        float inv = 1.0f / sum;
#pragma unroll
        for (int j = 0; j < 4; j++) p[i][j] *= inv;
    }
    __half* ob = g_O16 + (size_t)t0 * DMODEL + h * 128 + lane * 4;
#pragma unroll
    for (int i = 0; i < 4; i++) {
        float o0 = p[i][0]*v[0].x + p[i][1]*v[1].x + p[i][2]*v[2].x + p[i][3]*v[3].x;
        float o1 = p[i][0]*v[0].y + p[i][1]*v[1].y + p[i][2]*v[2].y + p[i][3]*v[3].y;
        float o2 = p[i][0]*v[0].z + p[i][1]*v[1].z + p[i][2]*v[2].z + p[i][3]*v[3].z;
        float o3 = p[i][0]*v[0].w + p[i][1]*v[1].w + p[i][2]*v[2].w + p[i][3]*v[3].w;
        uint2 ov;
        __half2 h01 = __halves2half2(__float2half_rn(o0), __float2half_rn(o1));
        __half2 h23 = __halves2half2(__float2half_rn(o2), __float2half_rn(o3));
        ov.x = *(const uint32_t*)&h01;
        ov.y = *(const uint32_t*)&h23;
        *(uint2*)(ob + (size_t)i * DMODEL) = ov;
    }
}

// ----------------------------------------------------------------------------
extern "C" void kernel_launch(void* const* d_in, const int* in_sizes, int n_in,
                              void* d_out, int out_size)
{
    const float* x     = (const float*)d_in[0];
    const float* qk_w  = (const float*)d_in[1];
    const float* qk_b  = (const float*)d_in[2];
    const float* v_w   = (const float*)d_in[3];
    const float* v_b   = (const float*)d_in[4];
    const float* in_w  = (const float*)d_in[5];
    const float* in_b  = (const float*)d_in[6];
    const float* out_w = (const float*)d_in[7];
    const float* out_b = (const float*)d_in[8];
    float* out = (float*)d_out;
    (void)in_sizes; (void)n_in; (void)out_size;

    float *CF;
    __half *QKV16, *x16, *WF16, *O16, *ow16, *iw16, *qkT16, *vT16;
    cudaGetSymbolAddress((void**)&CF, g_CF);
    cudaGetSymbolAddress((void**)&QKV16, g_QKV16);
    cudaGetSymbolAddress((void**)&x16, g_x16);
    cudaGetSymbolAddress((void**)&WF16, g_WF16);
    cudaGetSymbolAddress((void**)&O16, g_O16);
    cudaGetSymbolAddress((void**)&ow16, g_ow16);
    cudaGetSymbolAddress((void**)&iw16, g_iw16);
    cudaGetSymbolAddress((void**)&qkT16, g_qkT16);
    cudaGetSymbolAddress((void**)&vT16, g_vT16);

    static bool init_done = false;
    static cudaStream_t s2;
    static cudaEvent_t evFork, evJoin;
    if (!init_done) {
        cudaFuncSetAttribute(gemm_fp16<true>,  cudaFuncAttributeMaxDynamicSharedMemorySize, H_SMEM_TOTAL);
        cudaFuncSetAttribute(gemm_fp16<false>, cudaFuncAttributeMaxDynamicSharedMemorySize, H_SMEM_TOTAL);
        cudaStreamCreateWithFlags(&s2, cudaStreamNonBlocking);
        cudaEventCreateWithFlags(&evFork, cudaEventDisableTiming);
        cudaEventCreateWithFlags(&evJoin, cudaEventDisableTiming);
        init_done = true;
    }

    // Fork: x conversion on s2, weight prep + fusion on the main stream.
    cudaEventRecord(evFork, 0);
    cudaStreamWaitEvent(s2, evFork, 0);
    xconv_kernel<<<XCONV_BLOCKS, 256, 0, s2>>>(x);

    wprep_kernel<<<WPREP_BLOCKS, 256>>>(in_w, out_w, qk_w, v_w, in_b, qk_b, v_b);
    gemm_fp16<true><<<dim3(DMODEL / 128, NQKV / 128), 128, H_SMEM_TOTAL>>>(
        iw16, qkT16, vT16, 2048, nullptr, nullptr, WF16, DMODEL, DMODEL);

    // Join: QKV needs both x16 and WF16.
    cudaEventRecord(evJoin, s2);
    cudaStreamWaitEvent(0, evJoin, 0);

    // QKV = X @ WF^T + CF  [32768, 3072], fp16 in/out
    gemm_fp16<true><<<dim3(NQKV / 128, NTOK / 128), 128, H_SMEM_TOTAL>>>(
        x16, WF16, nullptr, 0, CF, nullptr, QKV16, NQKV, DMODEL);
    // segment attention (fp16 -> fp16)
    attn_kernel<<<16384, 128>>>();
    // out = O @ out_w^T + out_b  [32768, 1024], fp16 -> fp32
    gemm_fp16<false><<<dim3(DMODEL / 128, NTOK / 128), 128, H_SMEM_TOTAL>>>(
        O16, ow16, nullptr, 0, out_b, out, nullptr, DMODEL, DMODEL);
}

// round 16
// speedup vs baseline: 1.0016x; 1.0016x over previous
#include <cuda_runtime.h>
#include <cuda_fp16.h>
#include <cstdint>
#include <math.h>

// B=8, S=4096, D=1024, H=8, SEG=4, head_dim=128.
// Padding dead; segment shuffle is a permutation -> segments = consecutive
// 4-token groups. Weights fused: WF = in_proj @ (Wqk|Wqk|Wv), CF = in_proj@b + b.
// All GEMMs single-pass fp16 mma.sync, fp32 accum (measured rel_err 5.49e-4).
// GEMM shape locked by R14 (CTA 128x128, 4 warps 64x64, 4 stages, 2 CTAs/SM;
// 128 B smem/MMA = crossbar-even). R15 fork/join was neutral -> single stream.
// R16: software-pipelined fragments -- load BOTH kc-halves' ldmatrix fragments
// up front so kc1's LDSM overlaps kc0's MMA burst (tensor 61% -> target ~75%).

#define DMODEL 1024
#define NTOK   32768
#define NQKV   3072

#define HSTAGE 4
#define ROWB   80u
#define A_ROWS 128u
#define B_ROWS 128u
#define H_A_OFF 0u
#define H_B_OFF (A_ROWS * ROWB)                     // 10240
#define H_STAGE_BYTES ((A_ROWS + B_ROWS) * ROWB)    // 20480
#define H_SMEM_TOTAL (HSTAGE * H_STAGE_BYTES)       // 81920 -> 2 CTAs/SM

// ------------------------- device scratch (no allocs) -----------------------
__device__ __align__(256) float   g_CF[NQKV];
__device__ __align__(256) __half  g_QKV16[(size_t)NTOK * NQKV];
__device__ __align__(256) __half  g_x16[(size_t)NTOK * DMODEL];
__device__ __align__(256) __half  g_WF16[(size_t)NQKV * DMODEL];
__device__ __align__(256) __half  g_O16[(size_t)NTOK * DMODEL];
__device__ __align__(256) __half  g_ow16[(size_t)DMODEL * DMODEL];
__device__ __align__(256) __half  g_iw16[(size_t)NQKV * DMODEL];
__device__ __align__(256) __half  g_qkT16[(size_t)DMODEL * DMODEL];
__device__ __align__(256) __half  g_vT16[(size_t)DMODEL * DMODEL];

// ------------------------------ helpers -------------------------------------
__device__ __forceinline__ uint32_t smem_u32(const void* p) {
    uint32_t a;
    asm("{ .reg .u64 t; cvta.to.shared.u64 t, %1; cvt.u32.u64 %0, t; }" : "=r"(a) : "l"(p));
    return a;
}
__device__ __forceinline__ void cp16(uint32_t dst, const void* src) {
    asm volatile("cp.async.cg.shared.global [%0], [%1], 16;" :: "r"(dst), "l"(src) : "memory");
}
#define CP_COMMIT() asm volatile("cp.async.commit_group;" ::: "memory")
#define CP_WAIT2()  asm volatile("cp.async.wait_group 2;" ::: "memory")

#define LDSM_X4(R, a) \
    asm volatile("ldmatrix.sync.aligned.m8n8.x4.shared.b16 {%0,%1,%2,%3}, [%4];" \
        : "=r"((R)[0]), "=r"((R)[1]), "=r"((R)[2]), "=r"((R)[3]) : "r"(a))

#define MMA_FP16(d, a, b0, b1) \
    asm volatile("mma.sync.aligned.m16n8k16.row.col.f32.f16.f16.f32 " \
        "{%0,%1,%2,%3}, {%4,%5,%6,%7}, {%8,%9}, {%0,%1,%2,%3};" \
        : "+f"((d)[0]), "+f"((d)[1]), "+f"((d)[2]), "+f"((d)[3]) \
        : "r"((a)[0]), "r"((a)[1]), "r"((a)[2]), "r"((a)[3]), "r"(b0), "r"(b1))

// ----------------------------------------------------------------------------
// Single-pass fp16 GEMM: C[M,Ntot] = A@B^T (+bias).
// CTA 128x128, BK=32, 128 threads (4 warps, 2Mx2N, warp 64x64), 4 stages,
// 2 CTAs/SM. Fragments for both k16 halves are loaded before the MMA phases
// (software pipelining: kc1 LDSM overlaps kc0 MMAs).
// OUT16=true -> fp16 C16; false -> fp32 C.
// ----------------------------------------------------------------------------
template <bool OUT16>
__global__ void __launch_bounds__(128, 2)
gemm_fp16(const __half* __restrict__ A,
          const __half* __restrict__ B, const __half* __restrict__ B2, int b2row,
          const float* __restrict__ bias, float* __restrict__ C,
          __half* __restrict__ C16, int Ntot, int K)
{
    extern __shared__ char smem[];
    const uint32_t sb = smem_u32(smem);
    const int tid = threadIdx.x, wid = tid >> 5, lane = tid & 31;
    const int m0 = blockIdx.y * 128, n0 = blockIdx.x * 128;
    const int KT = K >> 5;
    const __half* Bp = (B2 != nullptr && m0 >= b2row) ? B2 : B;

    const int wm = (wid & 1) * 64;       // 2 warps in M
    const int wn = (wid >> 1) * 64;      // 2 warps in N
    const int g = lane >> 3, r = lane & 7;

    const uint32_t aRow = (uint32_t)(wm + (g & 1) * 8 + r);
    const uint32_t aCk  = (uint32_t)(g >> 1);
    const uint32_t bRow = (uint32_t)(wn + (g >> 1) * 8 + r);
    const uint32_t bCk  = (uint32_t)(g & 1);

    float acc[4][8][4];
#pragma unroll
    for (int i = 0; i < 4; i++)
#pragma unroll
        for (int j = 0; j < 8; j++)
#pragma unroll
            for (int q = 0; q < 4; q++) acc[i][j][q] = 0.0f;

    auto load_tile = [&](int kt, int s) {
        const int k0 = kt << 5;
        const uint32_t sbase = sb + (uint32_t)s * H_STAGE_BYTES;
#pragma unroll
        for (int q = 0; q < 8; q++) {
            int c = tid + q * 128;
            const __half* src;
            uint32_t dst;
            if (c < 512) {
                int rr = c >> 2, ck = c & 3;
                src = A + (size_t)(m0 + rr) * K + k0 + ck * 8;
                dst = sbase + H_A_OFF + (uint32_t)rr * ROWB + (uint32_t)ck * 16u;
            } else {
                int cc = c - 512;
                int rr = cc >> 2, ck = cc & 3;
                src = Bp + (size_t)(n0 + rr) * K + k0 + ck * 8;
                dst = sbase + H_B_OFF + (uint32_t)rr * ROWB + (uint32_t)ck * 16u;
            }
            cp16(dst, src);
        }
    };

    load_tile(0, 0); CP_COMMIT();
    load_tile(1, 1); CP_COMMIT();
    load_tile(2, 2); CP_COMMIT();

    for (int kt = 0; kt < KT; kt++) {
        CP_WAIT2();
        __syncthreads();
        if (kt + 3 < KT) load_tile(kt + 3, (kt + 3) % HSTAGE);
        CP_COMMIT();

        const uint32_t sbase = sb + (uint32_t)(kt % HSTAGE) * H_STAGE_BYTES;

        // Load fragments for BOTH k16 halves up front (kc1 LDSM overlaps kc0 MMA)
        uint32_t af0[4][4], bf0[4][4], af1[4][4], bf1[4][4];
#pragma unroll
        for (int mi = 0; mi < 4; mi++)
            LDSM_X4(af0[mi], sbase + H_A_OFF + (aRow + mi * 16) * ROWB + aCk * 16u);
#pragma unroll
        for (int bj = 0; bj < 4; bj++)
            LDSM_X4(bf0[bj], sbase + H_B_OFF + (bRow + bj * 16) * ROWB + bCk * 16u);
#pragma unroll
        for (int mi = 0; mi < 4; mi++)
            LDSM_X4(af1[mi], sbase + H_A_OFF + (aRow + mi * 16) * ROWB + 32u + aCk * 16u);
#pragma unroll
        for (int bj = 0; bj < 4; bj++)
            LDSM_X4(bf1[bj], sbase + H_B_OFF + (bRow + bj * 16) * ROWB + 32u + bCk * 16u);

#pragma unroll
        for (int mi = 0; mi < 4; mi++)
#pragma unroll
            for (int nj = 0; nj < 8; nj++)
                MMA_FP16(acc[mi][nj], af0[mi],
                         bf0[nj >> 1][(nj & 1) * 2], bf0[nj >> 1][(nj & 1) * 2 + 1]);
#pragma unroll
        for (int mi = 0; mi < 4; mi++)
#pragma unroll
            for (int nj = 0; nj < 8; nj++)
                MMA_FP16(acc[mi][nj], af1[mi],
                         bf1[nj >> 1][(nj & 1) * 2], bf1[nj >> 1][(nj & 1) * 2 + 1]);
    }

    const int rb = lane >> 2, cb = (lane & 3) * 2;
#pragma unroll
    for (int mi = 0; mi < 4; mi++) {
#pragma unroll
        for (int nj = 0; nj < 8; nj++) {
            int row0 = m0 + wm + mi * 16 + rb;
            int col = n0 + wn + nj * 8 + cb;
            float b0 = bias ? bias[col] : 0.0f;
            float b1 = bias ? bias[col + 1] : 0.0f;
            float v0 = acc[mi][nj][0] + b0, v1 = acc[mi][nj][1] + b1;
            float v2 = acc[mi][nj][2] + b0, v3 = acc[mi][nj][3] + b1;
            if (OUT16) {
                *(__half2*)(C16 + (size_t)row0 * Ntot + col) =
                    __halves2half2(__float2half_rn(v0), __float2half_rn(v1));
                *(__half2*)(C16 + (size_t)(row0 + 8) * Ntot + col) =
                    __halves2half2(__float2half_rn(v2), __float2half_rn(v3));
            } else {
                *(float2*)(C + (size_t)row0 * Ntot + col) = make_float2(v0, v1);
                *(float2*)(C + (size_t)(row0 + 8) * Ntot + col) = make_float2(v2, v3);
            }
        }
    }
}

// ------------------- prep kernels (two independent chains) -------------------
#define N4_X  (NTOK * DMODEL / 4)            // 8388608
#define N4_IW (NQKV * DMODEL / 4)            // 786432
#define N4_OW (DMODEL * DMODEL / 4)          // 262144
#define XCONV_BLOCKS (N4_X / 1024)           // 8192
#define WCONV_BLOCKS ((N4_IW + N4_OW) / 1024)// 1024
#define TRANS_BLOCKS 2048                    // 32*32*2
#define BIAS_BLOCKS 384
#define WPREP_BLOCKS (WCONV_BLOCKS + TRANS_BLOCKS + BIAS_BLOCKS)

__global__ void xconv_kernel(const float* __restrict__ x)
{
    int j0 = blockIdx.x * 1024 + threadIdx.x;
#pragma unroll
    for (int q = 0; q < 4; q++) {
        int j = j0 + q * 256;
        float4 v = ((const float4*)x)[j];
        ((__half2*)g_x16)[2 * j + 0] = __halves2half2(__float2half_rn(v.x), __float2half_rn(v.y));
        ((__half2*)g_x16)[2 * j + 1] = __halves2half2(__float2half_rn(v.z), __float2half_rn(v.w));
    }
}

__global__ void wprep_kernel(const float* __restrict__ iw,
                             const float* __restrict__ ow,
                             const float* __restrict__ qk_w,
                             const float* __restrict__ v_w,
                             const float* __restrict__ in_b,
                             const float* __restrict__ bqk,
                             const float* __restrict__ bv)
{
    __shared__ float t[32][33];
    const int b = blockIdx.x, tid = threadIdx.x;

    if (b < WCONV_BLOCKS) {
        int j0 = b * 1024 + tid;
#pragma unroll
        for (int q = 0; q < 4; q++) {
            int j = j0 + q * 256;
            const float* in;
            __half* out;
            if (j < N4_IW) { in = iw; out = g_iw16; }
            else { j -= N4_IW; in = ow; out = g_ow16; }
            float4 v = ((const float4*)in)[j];
            ((__half2*)out)[2 * j + 0] = __halves2half2(__float2half_rn(v.x), __float2half_rn(v.y));
            ((__half2*)out)[2 * j + 1] = __halves2half2(__float2half_rn(v.z), __float2half_rn(v.w));
        }
    } else if (b < WCONV_BLOCKS + TRANS_BLOCKS) {
        int bb = b - WCONV_BLOCKS;
        int z = bb >> 10, rem = bb & 1023;
        const float* W = z ? v_w : qk_w;
        __half* T = z ? g_vT16 : g_qkT16;
        int bx = (rem & 31) * 32, by = (rem >> 5) * 32;
        int tx = tid & 31, ty = tid >> 5;     // 32 x 8
        for (int j = ty; j < 32; j += 8)
            t[j][tx] = W[(size_t)(by + j) * DMODEL + bx + tx];
        __syncthreads();
        for (int j = ty; j < 32; j += 8)
            T[(size_t)(bx + j) * DMODEL + by + tx] = __float2half_rn(t[tx][j]);
    } else {
        int bb = b - WCONV_BLOCKS - TRANS_BLOCKS;
        int gw = (bb * 256 + tid) >> 5;
        int lane = tid & 31;
        if (gw < NQKV) {
            const float* bvec = (gw < 2048) ? bqk : bv;
            const float* Arow = iw + (size_t)gw * DMODEL;
            float s = 0.0f;
            for (int j = lane; j < DMODEL; j += 32) s += Arow[j] * bvec[j];
#pragma unroll
            for (int off = 16; off; off >>= 1) s += __shfl_xor_sync(0xffffffffu, s, off);
            if (lane == 0) g_CF[gw] = s + in_b[gw];
        }
    }
}

// -------- segment attention (SEG=4, per head), 8B vector loads/stores --------
__global__ void attn_kernel()
{
    int gw   = (int)((blockIdx.x * blockDim.x + threadIdx.x) >> 5);
    int lane = threadIdx.x & 31;
    if (gw >= (NTOK / 4) * 8) return;
    int seg = gw >> 3, h = gw & 7, t0 = seg << 2;

    const __half* base = g_QKV16 + (size_t)t0 * NQKV + h * 128 + lane * 4;
    float4 q[4], k[4], v[4];
#pragma unroll
    for (int i = 0; i < 4; i++) {
        uint2 qr = *(const uint2*)(base + (size_t)i * NQKV);
        uint2 kr = *(const uint2*)(base + (size_t)i * NQKV + 1024);
        uint2 vr = *(const uint2*)(base + (size_t)i * NQKV + 2048);
        float2 q0 = __half22float2(*(const __half2*)&qr.x), q1 = __half22float2(*(const __half2*)&qr.y);
        float2 k0 = __half22float2(*(const __half2*)&kr.x), k1 = __half22float2(*(const __half2*)&kr.y);
        float2 v0 = __half22float2(*(const __half2*)&vr.x), v1 = __half22float2(*(const __half2*)&vr.y);
        q[i] = make_float4(q0.x, q0.y, q1.x, q1.y);
        k[i] = make_float4(k0.x, k0.y, k1.x, k1.y);
        v[i] = make_float4(v0.x, v0.y, v1.x, v1.y);
    }
    float s[4][4];
#pragma unroll
    for (int i = 0; i < 4; i++)
#pragma unroll
        for (int j = 0; j < 4; j++)
            s[i][j] = q[i].x * k[j].x + q[i].y * k[j].y + q[i].z * k[j].z + q[i].w * k[j].w;
#pragma unroll
    for (int off = 16; off; off >>= 1)
#pragma unroll
        for (int i = 0; i < 4; i++)
#pragma unroll
            for (int j = 0; j < 4; j++)
                s[i][j] += __shfl_xor_sync(0xffffffffu, s[i][j], off);

    const float scale = 0.08838834764831845f;
    float p[4][4];
#pragma unroll
    for (int i = 0; i < 4; i++) {
        float m = -1e30f;
#pragma unroll
        for (int j = 0; j < 4; j++) {
            float sv = (j == i) ? -1e30f : s[i][j] * scale;
            p[i][j] = sv; m = fmaxf(m, sv);
        }
        float sum = 0.0f;
#pragma unroll
        for (int j = 0; j < 4; j++) { p[i][j] = expf(p[i][j] - m); sum += p[i][j]; }
        float inv = 1.0f / sum;
#pragma unroll
        for (int j = 0; j < 4; j++) p[i][j] *= inv;
    }
    __half* ob = g_O16 + (size_t)t0 * DMODEL + h * 128 + lane * 4;
#pragma unroll
    for (int i = 0; i < 4; i++) {
        float o0 = p[i][0]*v[0].x + p[i][1]*v[1].x + p[i][2]*v[2].x + p[i][3]*v[3].x;
        float o1 = p[i][0]*v[0].y + p[i][1]*v[1].y + p[i][2]*v[2].y + p[i][3]*v[3].y;
        float o2 = p[i][0]*v[0].z + p[i][1]*v[1].z + p[i][2]*v[2].z + p[i][3]*v[3].z;
        float o3 = p[i][0]*v[0].w + p[i][1]*v[1].w + p[i][2]*v[2].w + p[i][3]*v[3].w;
        uint2 ov;
        __half2 h01 = __halves2half2(__float2half_rn(o0), __float2half_rn(o1));
        __half2 h23 = __halves2half2(__float2half_rn(o2), __float2half_rn(o3));
        ov.x = *(const uint32_t*)&h01;
        ov.y = *(const uint32_t*)&h23;
        *(uint2*)(ob + (size_t)i * DMODEL) = ov;
    }
}

// ----------------------------------------------------------------------------
extern "C" void kernel_launch(void* const* d_in, const int* in_sizes, int n_in,
                              void* d_out, int out_size)
{
    const float* x     = (const float*)d_in[0];
    const float* qk_w  = (const float*)d_in[1];
    const float* qk_b  = (const float*)d_in[2];
    const float* v_w   = (const float*)d_in[3];
    const float* v_b   = (const float*)d_in[4];
    const float* in_w  = (const float*)d_in[5];
    const float* in_b  = (const float*)d_in[6];
    const float* out_w = (const float*)d_in[7];
    const float* out_b = (const float*)d_in[8];
    float* out = (float*)d_out;
    (void)in_sizes; (void)n_in; (void)out_size;

    float *CF;
    __half *QKV16, *x16, *WF16, *O16, *ow16, *iw16, *qkT16, *vT16;
    cudaGetSymbolAddress((void**)&CF, g_CF);
    cudaGetSymbolAddress((void**)&QKV16, g_QKV16);
    cudaGetSymbolAddress((void**)&x16, g_x16);
    cudaGetSymbolAddress((void**)&WF16, g_WF16);
    cudaGetSymbolAddress((void**)&O16, g_O16);
    cudaGetSymbolAddress((void**)&ow16, g_ow16);
    cudaGetSymbolAddress((void**)&iw16, g_iw16);
    cudaGetSymbolAddress((void**)&qkT16, g_qkT16);
    cudaGetSymbolAddress((void**)&vT16, g_vT16);

    static bool attr_set = false;
    if (!attr_set) {
        cudaFuncSetAttribute(gemm_fp16<true>,  cudaFuncAttributeMaxDynamicSharedMemorySize, H_SMEM_TOTAL);
        cudaFuncSetAttribute(gemm_fp16<false>, cudaFuncAttributeMaxDynamicSharedMemorySize, H_SMEM_TOTAL);
        attr_set = true;
    }

    // 0) prep: weights branch first (fusion depends on it), then x conversion
    wprep_kernel<<<WPREP_BLOCKS, 256>>>(in_w, out_w, qk_w, v_w, in_b, qk_b, v_b);
    xconv_kernel<<<XCONV_BLOCKS, 256>>>(x);
    // 1) weight fusion (rows >= 2048 use vT16)
    gemm_fp16<true><<<dim3(DMODEL / 128, NQKV / 128), 128, H_SMEM_TOTAL>>>(
        iw16, qkT16, vT16, 2048, nullptr, nullptr, WF16, DMODEL, DMODEL);
    // 2) QKV = X @ WF^T + CF  [32768, 3072], fp16 in/out
    gemm_fp16<true><<<dim3(NQKV / 128, NTOK / 128), 128, H_SMEM_TOTAL>>>(
        x16, WF16, nullptr, 0, CF, nullptr, QKV16, NQKV, DMODEL);
    // 3) segment attention (fp16 -> fp16)
    attn_kernel<<<16384, 128>>>();
    // 4) out = O @ out_w^T + out_b  [32768, 1024], fp16 -> fp32
    gemm_fp16<false><<<dim3(DMODEL / 128, NTOK / 128), 128, H_SMEM_TOTAL>>>(
        O16, ow16, nullptr, 0, out_b, out, nullptr, DMODEL, DMODEL);
}